// round 1
// baseline (speedup 1.0000x reference)
#include <cuda_runtime.h>

#define MSA_S 256
#define NRES  384
#define C     32
#define CZ    128
#define TI    4
#define TJ    4
#define KC    32

// scratch: a = LN(m)@W1, b = LN(m)@W2, layout [S][N][C] fp32
__device__ float g_a[MSA_S * NRES * C];
__device__ float g_b[MSA_S * NRES * C];

// -------------------------------------------------------------------------
// Kernel 1: fused LayerNorm + dual projection. One warp per (s,i) row.
// -------------------------------------------------------------------------
__global__ void ln_proj_kernel(const float* __restrict__ m,
                               const float* __restrict__ gamma,
                               const float* __restrict__ beta,
                               const float* __restrict__ W1,
                               const float* __restrict__ W2) {
    int row  = blockIdx.x * blockDim.y + threadIdx.y;   // [0, S*N)
    int lane = threadIdx.x;                              // channel c

    float v = m[row * C + lane];
    float s = v;
    #pragma unroll
    for (int o = 16; o; o >>= 1) s += __shfl_xor_sync(0xffffffffu, s, o);
    float mu = s * (1.0f / C);
    float d  = v - mu;
    float q  = d * d;
    #pragma unroll
    for (int o = 16; o; o >>= 1) q += __shfl_xor_sync(0xffffffffu, q, o);
    float rstd = rsqrtf(q * (1.0f / C) + 1e-5f);
    float mn = d * rstd * gamma[lane] + beta[lane];

    float accA = 0.f, accB = 0.f;
    #pragma unroll
    for (int c = 0; c < C; c++) {
        float mv = __shfl_sync(0xffffffffu, mn, c);
        accA += mv * W1[c * C + lane];
        accB += mv * W2[c * C + lane];
    }
    g_a[row * C + lane] = accA;
    g_b[row * C + lane] = accB;
}

// -------------------------------------------------------------------------
// Kernel 2: fused outer-product-mean + W3 projection.
// CTA = 4x4 (i,j) residue tile. 256 threads.
// Phase 1: O[128x128] = sum_s A[s, 4i x 32c]^T B[s, 4j x 32d]   (regs)
// Phase 2: O -> smem re-indexed [pair16][cd1024]; z = O/S @ W3 + b3
// Dynamic smem: 64 KB (As/Bs 32 KB during phase 1, O 64 KB after).
// -------------------------------------------------------------------------
__global__ void __launch_bounds__(256, 2)
opm_kernel(const float* __restrict__ W3,
           const float* __restrict__ b3,
           float* __restrict__ z) {
    extern __shared__ float sm[];           // 16384 floats
    float* As = sm;                          // [KC][128]
    float* Bs = sm + KC * 128;               // [KC][128]

    const int bi = blockIdx.y, bj = blockIdx.x;
    const int t  = threadIdx.x;
    const int ty = t >> 4, tx = t & 15;

    const float* aBase = g_a + bi * (TI * C);
    const float* bBase = g_b + bj * (TJ * C);

    float acc[8][8];
    #pragma unroll
    for (int r = 0; r < 8; r++)
        #pragma unroll
        for (int c = 0; c < 8; c++) acc[r][c] = 0.f;

    const int lr = t >> 5;     // base row for loads (0..7)
    const int lc = t & 31;     // float4 slot in row (0..31)

    for (int s0 = 0; s0 < MSA_S; s0 += KC) {
        #pragma unroll
        for (int r4 = 0; r4 < 4; r4++) {
            int k = lr + r4 * 8;
            long goff = (long)(s0 + k) * (NRES * C) + lc * 4;
            float4 va = *(const float4*)(aBase + goff);
            float4 vb = *(const float4*)(bBase + goff);
            *(float4*)(As + k * 128 + lc * 4) = va;
            *(float4*)(Bs + k * 128 + lc * 4) = vb;
        }
        __syncthreads();

        #pragma unroll 8
        for (int k = 0; k < KC; k++) {
            float af[8], bf[8];
            *(float4*)(af)     = *(const float4*)(As + k * 128 + ty * 8);
            *(float4*)(af + 4) = *(const float4*)(As + k * 128 + ty * 8 + 4);
            *(float4*)(bf)     = *(const float4*)(Bs + k * 128 + tx * 8);
            *(float4*)(bf + 4) = *(const float4*)(Bs + k * 128 + tx * 8 + 4);
            #pragma unroll
            for (int r = 0; r < 8; r++)
                #pragma unroll
                for (int c = 0; c < 8; c++)
                    acc[r][c] += af[r] * bf[c];
        }
        __syncthreads();
    }

    // Phase 1.5: scatter O into smem as [pair = i_loc*4+j_loc][c*32+d]
    #pragma unroll
    for (int rr = 0; rr < 8; rr++) {
        int r = ty * 8 + rr;                 // i_loc*32 + c
        #pragma unroll
        for (int cc = 0; cc < 8; cc++) {
            int cidx = tx * 8 + cc;          // j_loc*32 + d
            sm[(r >> 5) * 4096 + (cidx >> 5) * 1024 + (r & 31) * 32 + (cidx & 31)]
                = acc[rr][cc];
        }
    }
    __syncthreads();

    // Phase 2: z[pair, e0..e0+8) = (O[pair,:]/S) @ W3[:, e0..e0+8) + b3
    const int p  = t >> 4;                   // pair 0..15
    const int e0 = (t & 15) * 8;             // output channel base
    const float* op = sm + p * 1024;

    float zacc[8];
    #pragma unroll
    for (int q = 0; q < 8; q++) zacc[q] = 0.f;

    for (int k = 0; k < C * C; k += 4) {
        float4 ov = *(const float4*)(op + k);
        float ovv[4] = {ov.x, ov.y, ov.z, ov.w};
        #pragma unroll
        for (int kk = 0; kk < 4; kk++) {
            float o = ovv[kk];
            float4 w0 = __ldg((const float4*)(W3 + (long)(k + kk) * CZ + e0));
            float4 w1 = __ldg((const float4*)(W3 + (long)(k + kk) * CZ + e0 + 4));
            zacc[0] += o * w0.x; zacc[1] += o * w0.y;
            zacc[2] += o * w0.z; zacc[3] += o * w0.w;
            zacc[4] += o * w1.x; zacc[5] += o * w1.y;
            zacc[6] += o * w1.z; zacc[7] += o * w1.w;
        }
    }

    const float invS = 1.0f / MSA_S;
    int i = bi * TI + (p >> 2);
    int j = bj * TJ + (p & 3);
    float4 b30 = __ldg((const float4*)(b3 + e0));
    float4 b31 = __ldg((const float4*)(b3 + e0 + 4));
    float4 o0, o1;
    o0.x = zacc[0] * invS + b30.x; o0.y = zacc[1] * invS + b30.y;
    o0.z = zacc[2] * invS + b30.z; o0.w = zacc[3] * invS + b30.w;
    o1.x = zacc[4] * invS + b31.x; o1.y = zacc[5] * invS + b31.y;
    o1.z = zacc[6] * invS + b31.z; o1.w = zacc[7] * invS + b31.w;

    long zoff = ((long)i * NRES + j) * CZ + e0;
    *(float4*)(z + zoff)     = o0;
    *(float4*)(z + zoff + 4) = o1;
}

// -------------------------------------------------------------------------
extern "C" void kernel_launch(void* const* d_in, const int* in_sizes, int n_in,
                              void* d_out, int out_size) {
    const float* m     = (const float*)d_in[0];
    const float* gamma = (const float*)d_in[1];
    const float* beta  = (const float*)d_in[2];
    const float* W1    = (const float*)d_in[3];
    const float* W2    = (const float*)d_in[4];
    const float* W3    = (const float*)d_in[5];
    const float* b3    = (const float*)d_in[6];
    float* z = (float*)d_out;

    (void)in_sizes; (void)n_in; (void)out_size;

    cudaFuncSetAttribute(opm_kernel,
                         cudaFuncAttributeMaxDynamicSharedMemorySize, 65536);

    // LN + projections: S*N rows, 8 warps/CTA
    ln_proj_kernel<<<(MSA_S * NRES) / 8, dim3(32, 8)>>>(m, gamma, beta, W1, W2);

    // fused outer-product-mean + W3 projection
    opm_kernel<<<dim3(NRES / TJ, NRES / TI), 256, 65536>>>(W3, b3, z);
}

// round 2
// speedup vs baseline: 2.3012x; 2.3012x over previous
#include <cuda_runtime.h>

#define MSA_S 256
#define NRES  384
#define C     32
#define CZ    128
#define KC    32
#define NPAIR (NRES * NRES)      // 147456
#define CD    (C * C)            // 1024

// scratch
__device__ float g_a[MSA_S * NRES * C];            // LN(m) @ W1
__device__ float g_b[MSA_S * NRES * C];            // LN(m) @ W2
__device__ float g_o[(size_t)NPAIR * CD];          // O / S  (604 MB)

// ---------------- packed fp32x2 helpers (Blackwell) -----------------------
__device__ __forceinline__ unsigned long long pack2(float x, float y) {
    unsigned long long r;
    asm("mov.b64 %0, {%1, %2};" : "=l"(r) : "f"(x), "f"(y));
    return r;
}
__device__ __forceinline__ void unpack2(unsigned long long v, float& x, float& y) {
    asm("mov.b64 {%0, %1}, %2;" : "=f"(x), "=f"(y) : "l"(v));
}
__device__ __forceinline__ void ffma2(unsigned long long& d,
                                      unsigned long long a,
                                      unsigned long long b) {
    asm("fma.rn.f32x2 %0, %1, %2, %0;" : "+l"(d) : "l"(a), "l"(b));
}

// -------------------------------------------------------------------------
// Kernel 1: fused LayerNorm + dual projection. One warp per (s,i) row.
// -------------------------------------------------------------------------
__global__ void ln_proj_kernel(const float* __restrict__ m,
                               const float* __restrict__ gamma,
                               const float* __restrict__ beta,
                               const float* __restrict__ W1,
                               const float* __restrict__ W2) {
    int row  = blockIdx.x * blockDim.y + threadIdx.y;
    int lane = threadIdx.x;

    float v = m[row * C + lane];
    float s = v;
    #pragma unroll
    for (int o = 16; o; o >>= 1) s += __shfl_xor_sync(0xffffffffu, s, o);
    float mu = s * (1.0f / C);
    float d  = v - mu;
    float q  = d * d;
    #pragma unroll
    for (int o = 16; o; o >>= 1) q += __shfl_xor_sync(0xffffffffu, q, o);
    float rstd = rsqrtf(q * (1.0f / C) + 1e-5f);
    float mn = d * rstd * gamma[lane] + beta[lane];

    float accA = 0.f, accB = 0.f;
    #pragma unroll
    for (int c = 0; c < C; c++) {
        float mv = __shfl_sync(0xffffffffu, mn, c);
        accA += mv * W1[c * C + lane];
        accB += mv * W2[c * C + lane];
    }
    g_a[row * C + lane] = accA;
    g_b[row * C + lane] = accB;
}

// -------------------------------------------------------------------------
// Kernel 2 (GEMM1): O[(i*384+j), c*32+d] = (1/S) * sum_s a[s,i,c] b[s,j,d]
// CTA = 4x4 residue tile -> 128x128 output tile, K = 256. f32x2 accum.
// -------------------------------------------------------------------------
__global__ void __launch_bounds__(256, 2)
gemm1_kernel(float* __restrict__ O) {
    __shared__ float As[KC * 128];
    __shared__ float Bs[KC * 128];

    const int bi = blockIdx.y, bj = blockIdx.x;
    const int t  = threadIdx.x;
    const int ty = t >> 4, tx = t & 15;

    const float* aBase = g_a + bi * (4 * C);
    const float* bBase = g_b + bj * (4 * C);

    unsigned long long acc[8][4];
    #pragma unroll
    for (int r = 0; r < 8; r++)
        #pragma unroll
        for (int c = 0; c < 4; c++) acc[r][c] = 0ull;

    const int lr = t >> 5;
    const int lc = t & 31;

    for (int s0 = 0; s0 < MSA_S; s0 += KC) {
        #pragma unroll
        for (int r4 = 0; r4 < 4; r4++) {
            int k = lr + r4 * 8;
            long goff = (long)(s0 + k) * (NRES * C) + lc * 4;
            *(float4*)(As + k * 128 + lc * 4) = *(const float4*)(aBase + goff);
            *(float4*)(Bs + k * 128 + lc * 4) = *(const float4*)(bBase + goff);
        }
        __syncthreads();

        #pragma unroll 8
        for (int k = 0; k < KC; k++) {
            float4 a0 = *(const float4*)(As + k * 128 + ty * 8);
            float4 a1 = *(const float4*)(As + k * 128 + ty * 8 + 4);
            float4 b0 = *(const float4*)(Bs + k * 128 + tx * 8);
            float4 b1 = *(const float4*)(Bs + k * 128 + tx * 8 + 4);
            unsigned long long bp[4] = {pack2(b0.x, b0.y), pack2(b0.z, b0.w),
                                        pack2(b1.x, b1.y), pack2(b1.z, b1.w)};
            float af[8] = {a0.x, a0.y, a0.z, a0.w, a1.x, a1.y, a1.z, a1.w};
            #pragma unroll
            for (int r = 0; r < 8; r++) {
                unsigned long long ar = pack2(af[r], af[r]);
                #pragma unroll
                for (int c = 0; c < 4; c++) ffma2(acc[r][c], ar, bp[c]);
            }
        }
        __syncthreads();
    }

    // epilogue: scale by 1/S, write O row-major [pair][c*32+d]
    const float invS = 1.0f / MSA_S;
    const int j_loc = tx >> 2;
    const int d0    = (tx & 3) * 8;
    #pragma unroll
    for (int rr = 0; rr < 8; rr++) {
        int r  = ty * 8 + rr;
        int gi = bi * 4 + (r >> 5);
        int c  = r & 31;
        long orow = ((long)gi * NRES + bj * 4 + j_loc) * CD + c * 32 + d0;
        float f[8];
        #pragma unroll
        for (int c4 = 0; c4 < 4; c4++) unpack2(acc[rr][c4], f[c4 * 2], f[c4 * 2 + 1]);
        float4 v0 = {f[0] * invS, f[1] * invS, f[2] * invS, f[3] * invS};
        float4 v1 = {f[4] * invS, f[5] * invS, f[6] * invS, f[7] * invS};
        *(float4*)(O + orow)     = v0;
        *(float4*)(O + orow + 4) = v1;
    }
}

// -------------------------------------------------------------------------
// Kernel 3 (GEMM2): z[m, e] = O[m, :] @ W3[:, e] + b3[e]
// M = 147456, N = 128, K = 1024. CTA tile 128(M) x 128(N), K-slab 32.
// -------------------------------------------------------------------------
#define PAD 132   // 32-k row pitch in floats (keeps 16B alignment, avoids conflicts)

__global__ void __launch_bounds__(256, 2)
gemm2_kernel(const float* __restrict__ O,
             const float* __restrict__ W3,
             const float* __restrict__ b3,
             float* __restrict__ z) {
    __shared__ float As[32 * PAD];   // [k][m]
    __shared__ float Ws[32 * PAD];   // [k][e]

    const int mb = blockIdx.x;
    const int t  = threadIdx.x;
    const int ty = t >> 4, tx = t & 15;

    unsigned long long acc[8][4];
    #pragma unroll
    for (int r = 0; r < 8; r++)
        #pragma unroll
        for (int c = 0; c < 4; c++) acc[r][c] = 0ull;

    const int lm = t >> 1;        // 0..127 : m within tile (A loads)
    const int lk = t & 1;         // pairs of k-quads
    const int wk = t >> 3;        // 0..31  : k row (W loads)
    const int wf = t & 7;         // float4 slot group

    for (int ks = 0; ks < CD; ks += 32) {
        // load A tile [32k x 128m], transposed store
        #pragma unroll
        for (int it = 0; it < 4; it++) {
            int kq = lk + it * 2;                       // 0..7
            float4 v = *(const float4*)(O + (long)(mb * 128 + lm) * CD + ks + kq * 4);
            As[(kq * 4 + 0) * PAD + lm] = v.x;
            As[(kq * 4 + 1) * PAD + lm] = v.y;
            As[(kq * 4 + 2) * PAD + lm] = v.z;
            As[(kq * 4 + 3) * PAD + lm] = v.w;
        }
        // load W3 slab [32k x 128e]
        #pragma unroll
        for (int it = 0; it < 4; it++) {
            int f4 = wf + it * 8;                       // 0..31
            *(float4*)(Ws + wk * PAD + f4 * 4) =
                *(const float4*)(W3 + (long)(ks + wk) * CZ + f4 * 4);
        }
        __syncthreads();

        #pragma unroll 8
        for (int k = 0; k < 32; k++) {
            float4 a0 = *(const float4*)(As + k * PAD + ty * 8);
            float4 a1 = *(const float4*)(As + k * PAD + ty * 8 + 4);
            float4 b0 = *(const float4*)(Ws + k * PAD + tx * 8);
            float4 b1 = *(const float4*)(Ws + k * PAD + tx * 8 + 4);
            unsigned long long bp[4] = {pack2(b0.x, b0.y), pack2(b0.z, b0.w),
                                        pack2(b1.x, b1.y), pack2(b1.z, b1.w)};
            float af[8] = {a0.x, a0.y, a0.z, a0.w, a1.x, a1.y, a1.z, a1.w};
            #pragma unroll
            for (int r = 0; r < 8; r++) {
                unsigned long long ar = pack2(af[r], af[r]);
                #pragma unroll
                for (int c = 0; c < 4; c++) ffma2(acc[r][c], ar, bp[c]);
            }
        }
        __syncthreads();
    }

    // epilogue: + b3, store z
    float4 bb0 = *(const float4*)(b3 + tx * 8);
    float4 bb1 = *(const float4*)(b3 + tx * 8 + 4);
    #pragma unroll
    for (int rr = 0; rr < 8; rr++) {
        long m = (long)mb * 128 + ty * 8 + rr;
        float f[8];
        #pragma unroll
        for (int c4 = 0; c4 < 4; c4++) unpack2(acc[rr][c4], f[c4 * 2], f[c4 * 2 + 1]);
        float4 v0 = {f[0] + bb0.x, f[1] + bb0.y, f[2] + bb0.z, f[3] + bb0.w};
        float4 v1 = {f[4] + bb1.x, f[5] + bb1.y, f[6] + bb1.z, f[7] + bb1.w};
        *(float4*)(z + m * CZ + tx * 8)     = v0;
        *(float4*)(z + m * CZ + tx * 8 + 4) = v1;
    }
}

// -------------------------------------------------------------------------
extern "C" void kernel_launch(void* const* d_in, const int* in_sizes, int n_in,
                              void* d_out, int out_size) {
    const float* m     = (const float*)d_in[0];
    const float* gamma = (const float*)d_in[1];
    const float* beta  = (const float*)d_in[2];
    const float* W1    = (const float*)d_in[3];
    const float* W2    = (const float*)d_in[4];
    const float* W3    = (const float*)d_in[5];
    const float* b3    = (const float*)d_in[6];
    float* z = (float*)d_out;
    (void)in_sizes; (void)n_in; (void)out_size;

    float* o_ptr;
    cudaGetSymbolAddress((void**)&o_ptr, g_o);

    ln_proj_kernel<<<(MSA_S * NRES) / 8, dim3(32, 8)>>>(m, gamma, beta, W1, W2);
    gemm1_kernel<<<dim3(NRES / 4, NRES / 4), 256>>>(o_ptr);
    gemm2_kernel<<<NPAIR / 128, 256>>>(o_ptr, W3, b3, z);
}

// round 4
// speedup vs baseline: 4.2746x; 1.8575x over previous
#include <cuda_runtime.h>
#include <cuda_bf16.h>
#include <cstdint>

#define MSA_S 256
#define NRES  384
#define C     32
#define CZ    128
#define IC    (NRES * C)          // 12288
#define NPAIR (NRES * NRES)       // 147456
#define CD    (C * C)             // 1024

// ------------------------------ scratch ----------------------------------
__device__ float g_a[MSA_S * IC];                  // LN(m)@W1  [s][ic]
__device__ float g_b[MSA_S * IC];                  // LN(m)@W2  [s][ic]
__device__ __nv_bfloat16 g_at_hi[IC * MSA_S];      // [ic][s]
__device__ __nv_bfloat16 g_at_lo[IC * MSA_S];
__device__ __nv_bfloat16 g_bt_hi[IC * MSA_S];
__device__ __nv_bfloat16 g_bt_lo[IC * MSA_S];
__device__ __nv_bfloat16 g_w3t_hi[CZ * CD];        // [e][cd]
__device__ __nv_bfloat16 g_w3t_lo[CZ * CD];
__device__ __nv_bfloat16 g_o_hi[(size_t)NPAIR * CD];   // 302 MB
__device__ __nv_bfloat16 g_o_lo[(size_t)NPAIR * CD];   // 302 MB

// --------------------------- helpers -------------------------------------
__device__ __forceinline__ uint32_t smem_u32(const void* p) {
    uint32_t a;
    asm("{ .reg .u64 t; cvta.to.shared.u64 t, %1; cvt.u32.u64 %0, t; }"
        : "=r"(a) : "l"(p));
    return a;
}
__device__ __forceinline__ void cp16(uint32_t saddr, const void* g) {
    asm volatile("cp.async.ca.shared.global [%0], [%1], 16;"
                 :: "r"(saddr), "l"(g) : "memory");
}
__device__ __forceinline__ void ldsm4(uint32_t* r, uint32_t addr) {
    asm volatile("ldmatrix.sync.aligned.m8n8.x4.shared.b16 {%0,%1,%2,%3}, [%4];"
                 : "=r"(r[0]), "=r"(r[1]), "=r"(r[2]), "=r"(r[3]) : "r"(addr));
}
__device__ __forceinline__ void mma16816(float* d, const uint32_t* a,
                                         const uint32_t* b) {
    asm volatile(
        "mma.sync.aligned.m16n8k16.row.col.f32.bf16.bf16.f32 "
        "{%0,%1,%2,%3}, {%4,%5,%6,%7}, {%8,%9}, {%0,%1,%2,%3};"
        : "+f"(d[0]), "+f"(d[1]), "+f"(d[2]), "+f"(d[3])
        : "r"(a[0]), "r"(a[1]), "r"(a[2]), "r"(a[3]), "r"(b[0]), "r"(b[1]));
}

#define KB     32
#define PITCH  80                 // bytes per smem row (32 bf16 + 16B pad)
#define TB     (128 * PITCH)      // 10240 B per tile buffer

// -------------------------------------------------------------------------
// Kernel 1: fused LayerNorm + dual projection. One warp per (s,i) row.
// -------------------------------------------------------------------------
__global__ void ln_proj_kernel(const float* __restrict__ m,
                               const float* __restrict__ gamma,
                               const float* __restrict__ beta,
                               const float* __restrict__ W1,
                               const float* __restrict__ W2) {
    int row  = blockIdx.x * blockDim.y + threadIdx.y;
    int lane = threadIdx.x;

    float v = m[row * C + lane];
    float s = v;
    #pragma unroll
    for (int o = 16; o; o >>= 1) s += __shfl_xor_sync(0xffffffffu, s, o);
    float mu = s * (1.0f / C);
    float d  = v - mu;
    float q  = d * d;
    #pragma unroll
    for (int o = 16; o; o >>= 1) q += __shfl_xor_sync(0xffffffffu, q, o);
    float rstd = rsqrtf(q * (1.0f / C) + 1e-5f);
    float mn = d * rstd * gamma[lane] + beta[lane];

    float accA = 0.f, accB = 0.f;
    #pragma unroll
    for (int c = 0; c < C; c++) {
        float mv = __shfl_sync(0xffffffffu, mn, c);
        accA += mv * W1[c * C + lane];
        accB += mv * W2[c * C + lane];
    }
    g_a[row * C + lane] = accA;
    g_b[row * C + lane] = accB;
}

// -------------------------------------------------------------------------
// Kernel 2: transpose [s][ic] fp32 -> [ic][s] bf16 hi/lo (a and b)
// -------------------------------------------------------------------------
__global__ void transpose_split_ab() {
    __shared__ float tile[32][33];
    const float* src = blockIdx.z ? g_b : g_a;
    __nv_bfloat16* dhi = blockIdx.z ? g_bt_hi : g_at_hi;
    __nv_bfloat16* dlo = blockIdx.z ? g_bt_lo : g_at_lo;
    int ic0 = blockIdx.x * 32, s0 = blockIdx.y * 32;
    int tx = threadIdx.x, ty = threadIdx.y;
    #pragma unroll
    for (int j = 0; j < 4; j++)
        tile[ty + j * 8][tx] = src[(size_t)(s0 + ty + j * 8) * IC + ic0 + tx];
    __syncthreads();
    #pragma unroll
    for (int j = 0; j < 4; j++) {
        float v = tile[tx][ty + j * 8];
        __nv_bfloat16 h = __float2bfloat16(v);
        __nv_bfloat16 l = __float2bfloat16(v - __bfloat162float(h));
        size_t o = (size_t)(ic0 + ty + j * 8) * MSA_S + s0 + tx;
        dhi[o] = h; dlo[o] = l;
    }
}

// -------------------------------------------------------------------------
// Kernel 3: W3 [cd][e] -> W3t [e][cd] bf16 hi/lo
// -------------------------------------------------------------------------
__global__ void transpose_split_w3(const float* __restrict__ W3) {
    __shared__ float tile[32][33];
    int cd0 = blockIdx.x * 32, e0 = blockIdx.y * 32;
    int tx = threadIdx.x, ty = threadIdx.y;
    #pragma unroll
    for (int j = 0; j < 4; j++)
        tile[ty + j * 8][tx] = W3[(size_t)(cd0 + ty + j * 8) * CZ + e0 + tx];
    __syncthreads();
    #pragma unroll
    for (int j = 0; j < 4; j++) {
        float v = tile[tx][ty + j * 8];
        __nv_bfloat16 h = __float2bfloat16(v);
        __nv_bfloat16 l = __float2bfloat16(v - __bfloat162float(h));
        size_t o = (size_t)(e0 + ty + j * 8) * CD + cd0 + tx;
        g_w3t_hi[o] = h; g_w3t_lo[o] = l;
    }
}

// -------------------------------------------------------------------------
// Kernel 4 (GEMM1, mma.sync): O[ic, jd] = (1/S) sum_k at[ic,k] bt[jd,k]
// K = 3 x 256 (hi/lo split). CTA 128x128, 8 warps, warp tile 32x64.
// Epilogue writes O as bf16 hi/lo in [pair][cd] layout.
// -------------------------------------------------------------------------
__global__ void __launch_bounds__(256, 2)
gemm1_mma() {
    __shared__ __align__(16) char smem[4 * TB];   // {A0,B0,A1,B1}

    const int bi = blockIdx.y, bj = blockIdx.x;
    const int tid = threadIdx.x, lane = tid & 31, wid = tid >> 5;
    const int wm = wid & 3, wn = wid >> 2;
    const uint32_t sbase = smem_u32(smem);

    const __nv_bfloat16* aSel[3] = {g_at_hi, g_at_hi, g_at_lo};
    const __nv_bfloat16* bSel[3] = {g_bt_hi, g_bt_lo, g_bt_hi};

    float acc[2][8][4];
    #pragma unroll
    for (int tm = 0; tm < 2; tm++)
        #pragma unroll
        for (int tn = 0; tn < 8; tn++)
            #pragma unroll
            for (int q = 0; q < 4; q++) acc[tm][tn][q] = 0.f;

    #define G1_LOAD(kb, buf) do {                                              \
        int p = (kb) >> 3, k0 = ((kb) & 7) * KB;                               \
        const __nv_bfloat16* A = aSel[p] + (size_t)(bi * 128) * MSA_S + k0;    \
        const __nv_bfloat16* B = bSel[p] + (size_t)(bj * 128) * MSA_S + k0;    \
        uint32_t sA = sbase + (buf) * 2 * TB, sB = sA + TB;                    \
        _Pragma("unroll")                                                      \
        for (int it = 0; it < 2; it++) {                                       \
            int idx = tid + it * 256, r = idx >> 2, ch = idx & 3;              \
            cp16(sA + r * PITCH + ch * 16, A + (size_t)r * MSA_S + ch * 8);    \
            cp16(sB + r * PITCH + ch * 16, B + (size_t)r * MSA_S + ch * 8);    \
        }                                                                      \
        asm volatile("cp.async.commit_group;" ::: "memory");                   \
    } while (0)

    G1_LOAD(0, 0);
    for (int kb = 0; kb < 24; kb++) {
        int buf = kb & 1;
        if (kb + 1 < 24) {
            G1_LOAD(kb + 1, buf ^ 1);
            asm volatile("cp.async.wait_group 1;" ::: "memory");
        } else {
            asm volatile("cp.async.wait_group 0;" ::: "memory");
        }
        __syncthreads();
        uint32_t sA = sbase + buf * 2 * TB, sB = sA + TB;
        #pragma unroll
        for (int ks = 0; ks < 2; ks++) {
            uint32_t a[2][4];
            #pragma unroll
            for (int tm = 0; tm < 2; tm++)
                ldsm4(a[tm], sA + (wm * 32 + tm * 16 + (lane & 15)) * PITCH
                             + ks * 32 + (lane >> 4) * 16);
            uint32_t b[8][2];
            #pragma unroll
            for (int tq = 0; tq < 4; tq++) {
                uint32_t r[4];
                ldsm4(r, sB + (wn * 64 + tq * 16 + ((lane >> 4) << 3) + (lane & 7)) * PITCH
                         + ks * 32 + ((lane >> 3) & 1) * 16);
                b[2 * tq][0] = r[0]; b[2 * tq][1] = r[1];
                b[2 * tq + 1][0] = r[2]; b[2 * tq + 1][1] = r[3];
            }
            #pragma unroll
            for (int tm = 0; tm < 2; tm++)
                #pragma unroll
                for (int tn = 0; tn < 8; tn++)
                    mma16816(acc[tm][tn], a[tm], b[tn]);
        }
        __syncthreads();
    }

    // epilogue: scale, split, scatter to [pair][cd]
    const float invS = 1.0f / MSA_S;
    const int r0 = lane >> 2, cp2 = (lane & 3) * 2;
    #pragma unroll
    for (int tm = 0; tm < 2; tm++) {
        #pragma unroll
        for (int tn = 0; tn < 8; tn++) {
            int jd = bj * 128 + wn * 64 + tn * 8 + cp2;
            int pcol = jd >> 5, d = jd & 31;
            #pragma unroll
            for (int h = 0; h < 2; h++) {
                int ic = bi * 128 + wm * 32 + tm * 16 + r0 + h * 8;
                float v0 = acc[tm][tn][2 * h]     * invS;
                float v1 = acc[tm][tn][2 * h + 1] * invS;
                __nv_bfloat16 h0 = __float2bfloat16(v0);
                __nv_bfloat16 h1 = __float2bfloat16(v1);
                __nv_bfloat16 l0 = __float2bfloat16(v0 - __bfloat162float(h0));
                __nv_bfloat16 l1 = __float2bfloat16(v1 - __bfloat162float(h1));
                size_t off = ((size_t)(ic >> 5) * NRES + pcol) * CD
                             + (ic & 31) * 32 + d;
                __nv_bfloat162 hh; hh.x = h0; hh.y = h1;
                __nv_bfloat162 ll; ll.x = l0; ll.y = l1;
                *(__nv_bfloat162*)(g_o_hi + off) = hh;
                *(__nv_bfloat162*)(g_o_lo + off) = ll;
            }
        }
    }
    #undef G1_LOAD
}

// -------------------------------------------------------------------------
// Kernel 5 (GEMM2, mma.sync): z[m,e] = O[m,:] @ W3t[e,:]^T + b3
// M = 147456, N = 128, K = 3 x 1024. CTA 128x128, warp tile 32x64.
// -------------------------------------------------------------------------
__global__ void __launch_bounds__(256, 2)
gemm2_mma(const float* __restrict__ b3, float* __restrict__ z) {
    __shared__ __align__(16) char smem[4 * TB];

    const int mb = blockIdx.x;
    const int tid = threadIdx.x, lane = tid & 31, wid = tid >> 5;
    const int wm = wid & 3, wn = wid >> 2;
    const uint32_t sbase = smem_u32(smem);

    const __nv_bfloat16* aSel[3] = {g_o_hi, g_o_hi, g_o_lo};
    const __nv_bfloat16* bSel[3] = {g_w3t_hi, g_w3t_lo, g_w3t_hi};

    float acc[2][8][4];
    #pragma unroll
    for (int tm = 0; tm < 2; tm++)
        #pragma unroll
        for (int tn = 0; tn < 8; tn++)
            #pragma unroll
            for (int q = 0; q < 4; q++) acc[tm][tn][q] = 0.f;

    #define G2_LOAD(kb, buf) do {                                              \
        int p = (kb) >> 5, k0 = ((kb) & 31) * KB;                              \
        const __nv_bfloat16* A = aSel[p] + (size_t)(mb * 128) * CD + k0;       \
        const __nv_bfloat16* B = bSel[p] + k0;                                 \
        uint32_t sA = sbase + (buf) * 2 * TB, sB = sA + TB;                    \
        _Pragma("unroll")                                                      \
        for (int it = 0; it < 2; it++) {                                       \
            int idx = tid + it * 256, r = idx >> 2, ch = idx & 3;              \
            cp16(sA + r * PITCH + ch * 16, A + (size_t)r * CD + ch * 8);       \
            cp16(sB + r * PITCH + ch * 16, B + (size_t)r * CD + ch * 8);       \
        }                                                                      \
        asm volatile("cp.async.commit_group;" ::: "memory");                   \
    } while (0)

    G2_LOAD(0, 0);
    for (int kb = 0; kb < 96; kb++) {
        int buf = kb & 1;
        if (kb + 1 < 96) {
            G2_LOAD(kb + 1, buf ^ 1);
            asm volatile("cp.async.wait_group 1;" ::: "memory");
        } else {
            asm volatile("cp.async.wait_group 0;" ::: "memory");
        }
        __syncthreads();
        uint32_t sA = sbase + buf * 2 * TB, sB = sA + TB;
        #pragma unroll
        for (int ks = 0; ks < 2; ks++) {
            uint32_t a[2][4];
            #pragma unroll
            for (int tm = 0; tm < 2; tm++)
                ldsm4(a[tm], sA + (wm * 32 + tm * 16 + (lane & 15)) * PITCH
                             + ks * 32 + (lane >> 4) * 16);
            uint32_t b[8][2];
            #pragma unroll
            for (int tq = 0; tq < 4; tq++) {
                uint32_t r[4];
                ldsm4(r, sB + (wn * 64 + tq * 16 + ((lane >> 4) << 3) + (lane & 7)) * PITCH
                         + ks * 32 + ((lane >> 3) & 1) * 16);
                b[2 * tq][0] = r[0]; b[2 * tq][1] = r[1];
                b[2 * tq + 1][0] = r[2]; b[2 * tq + 1][1] = r[3];
            }
            #pragma unroll
            for (int tm = 0; tm < 2; tm++)
                #pragma unroll
                for (int tn = 0; tn < 8; tn++)
                    mma16816(acc[tm][tn], a[tm], b[tn]);
        }
        __syncthreads();
    }

    const int r0 = lane >> 2, cp2 = (lane & 3) * 2;
    #pragma unroll
    for (int tm = 0; tm < 2; tm++) {
        #pragma unroll
        for (int tn = 0; tn < 8; tn++) {
            int e = wn * 64 + tn * 8 + cp2;
            float be0 = __ldg(b3 + e), be1 = __ldg(b3 + e + 1);
            #pragma unroll
            for (int h = 0; h < 2; h++) {
                size_t mrow = (size_t)mb * 128 + wm * 32 + tm * 16 + r0 + h * 8;
                float2 v;
                v.x = acc[tm][tn][2 * h]     + be0;
                v.y = acc[tm][tn][2 * h + 1] + be1;
                *(float2*)(z + mrow * CZ + e) = v;
            }
        }
    }
    #undef G2_LOAD
}

// -------------------------------------------------------------------------
extern "C" void kernel_launch(void* const* d_in, const int* in_sizes, int n_in,
                              void* d_out, int out_size) {
    const float* m     = (const float*)d_in[0];
    const float* gamma = (const float*)d_in[1];
    const float* beta  = (const float*)d_in[2];
    const float* W1    = (const float*)d_in[3];
    const float* W2    = (const float*)d_in[4];
    const float* W3    = (const float*)d_in[5];
    const float* b3    = (const float*)d_in[6];
    float* z = (float*)d_out;
    (void)in_sizes; (void)n_in; (void)out_size;

    ln_proj_kernel<<<(MSA_S * NRES) / 8, dim3(32, 8)>>>(m, gamma, beta, W1, W2);
    transpose_split_ab<<<dim3(IC / 32, MSA_S / 32, 2), dim3(32, 8)>>>();
    transpose_split_w3<<<dim3(CD / 32, CZ / 32), dim3(32, 8)>>>(W3);
    gemm1_mma<<<dim3(IC / 128, IC / 128), 256>>>();
    gemm2_mma<<<NPAIR / 128, 256>>>(b3, z);
}

// round 5
// speedup vs baseline: 11.5979x; 2.7132x over previous
#include <cuda_runtime.h>
#include <cuda_fp16.h>
#include <cstdint>

#define MSA_S 256
#define NRES  384
#define C     32
#define CZ    128
#define IC    (NRES * C)          // 12288
#define NPAIR (NRES * NRES)       // 147456
#define CD    (C * C)             // 1024

// ------------------------------ scratch ----------------------------------
__device__ float g_a[MSA_S * IC];                  // LN(m)@W1  [s][ic]
__device__ float g_b[MSA_S * IC];                  // LN(m)@W2  [s][ic]
__device__ __half g_at[IC * MSA_S];                // [ic][s] fp16
__device__ __half g_bt[IC * MSA_S];
__device__ __half g_w3t[CZ * CD];                  // [e][cd] fp16
__device__ __half g_o[(size_t)NPAIR * CD];         // 302 MB fp16

// --------------------------- helpers -------------------------------------
__device__ __forceinline__ uint32_t smem_u32(const void* p) {
    uint32_t a;
    asm("{ .reg .u64 t; cvta.to.shared.u64 t, %1; cvt.u32.u64 %0, t; }"
        : "=r"(a) : "l"(p));
    return a;
}
__device__ __forceinline__ void cp16(uint32_t saddr, const void* g) {
    asm volatile("cp.async.ca.shared.global [%0], [%1], 16;"
                 :: "r"(saddr), "l"(g) : "memory");
}
__device__ __forceinline__ void ldsm4(uint32_t* r, uint32_t addr) {
    asm volatile("ldmatrix.sync.aligned.m8n8.x4.shared.b16 {%0,%1,%2,%3}, [%4];"
                 : "=r"(r[0]), "=r"(r[1]), "=r"(r[2]), "=r"(r[3]) : "r"(addr));
}
__device__ __forceinline__ void mma16816(float* d, const uint32_t* a,
                                         const uint32_t* b) {
    asm volatile(
        "mma.sync.aligned.m16n8k16.row.col.f32.f16.f16.f32 "
        "{%0,%1,%2,%3}, {%4,%5,%6,%7}, {%8,%9}, {%0,%1,%2,%3};"
        : "+f"(d[0]), "+f"(d[1]), "+f"(d[2]), "+f"(d[3])
        : "r"(a[0]), "r"(a[1]), "r"(a[2]), "r"(a[3]), "r"(b[0]), "r"(b[1]));
}

#define KB     32
#define PITCH  80                 // bytes per smem row (32 fp16 + 16B pad)
#define TB     (128 * PITCH)      // 10240 B per tile buffer

// -------------------------------------------------------------------------
// Kernel 1: fused LayerNorm + dual projection. One warp per (s,i) row.
// -------------------------------------------------------------------------
__global__ void ln_proj_kernel(const float* __restrict__ m,
                               const float* __restrict__ gamma,
                               const float* __restrict__ beta,
                               const float* __restrict__ W1,
                               const float* __restrict__ W2) {
    int row  = blockIdx.x * blockDim.y + threadIdx.y;
    int lane = threadIdx.x;

    float v = m[row * C + lane];
    float s = v;
    #pragma unroll
    for (int o = 16; o; o >>= 1) s += __shfl_xor_sync(0xffffffffu, s, o);
    float mu = s * (1.0f / C);
    float d  = v - mu;
    float q  = d * d;
    #pragma unroll
    for (int o = 16; o; o >>= 1) q += __shfl_xor_sync(0xffffffffu, q, o);
    float rstd = rsqrtf(q * (1.0f / C) + 1e-5f);
    float mn = d * rstd * gamma[lane] + beta[lane];

    float accA = 0.f, accB = 0.f;
    #pragma unroll
    for (int c = 0; c < C; c++) {
        float mv = __shfl_sync(0xffffffffu, mn, c);
        accA += mv * W1[c * C + lane];
        accB += mv * W2[c * C + lane];
    }
    g_a[row * C + lane] = accA;
    g_b[row * C + lane] = accB;
}

// -------------------------------------------------------------------------
// Kernel 2: transpose [s][ic] fp32 -> [ic][s] fp16 (a and b)
// -------------------------------------------------------------------------
__global__ void transpose_half_ab() {
    __shared__ float tile[32][33];
    const float* src = blockIdx.z ? g_b : g_a;
    __half* dst = blockIdx.z ? g_bt : g_at;
    int ic0 = blockIdx.x * 32, s0 = blockIdx.y * 32;
    int tx = threadIdx.x, ty = threadIdx.y;
    #pragma unroll
    for (int j = 0; j < 4; j++)
        tile[ty + j * 8][tx] = src[(size_t)(s0 + ty + j * 8) * IC + ic0 + tx];
    __syncthreads();
    #pragma unroll
    for (int j = 0; j < 4; j++) {
        size_t o = (size_t)(ic0 + ty + j * 8) * MSA_S + s0 + tx;
        dst[o] = __float2half(tile[tx][ty + j * 8]);
    }
}

// -------------------------------------------------------------------------
// Kernel 3: W3 [cd][e] -> W3t [e][cd] fp16
// -------------------------------------------------------------------------
__global__ void transpose_half_w3(const float* __restrict__ W3) {
    __shared__ float tile[32][33];
    int cd0 = blockIdx.x * 32, e0 = blockIdx.y * 32;
    int tx = threadIdx.x, ty = threadIdx.y;
    #pragma unroll
    for (int j = 0; j < 4; j++)
        tile[ty + j * 8][tx] = W3[(size_t)(cd0 + ty + j * 8) * CZ + e0 + tx];
    __syncthreads();
    #pragma unroll
    for (int j = 0; j < 4; j++) {
        size_t o = (size_t)(e0 + ty + j * 8) * CD + cd0 + tx;
        g_w3t[o] = __float2half(tile[tx][ty + j * 8]);
    }
}

// -------------------------------------------------------------------------
// Kernel 4 (GEMM1, fp16 mma.sync): O[ic, jd] = (1/S) sum_k at[ic,k] bt[jd,k]
// K = 256. CTA 128x128, 8 warps, warp tile 32x64. Epilogue -> fp16 O [pair][cd]
// -------------------------------------------------------------------------
__global__ void __launch_bounds__(256, 2)
gemm1_mma() {
    __shared__ __align__(16) char smem[4 * TB];   // {A0,B0,A1,B1}

    const int bi = blockIdx.y, bj = blockIdx.x;
    const int tid = threadIdx.x, lane = tid & 31, wid = tid >> 5;
    const int wm = wid & 3, wn = wid >> 2;
    const uint32_t sbase = smem_u32(smem);

    float acc[2][8][4];
    #pragma unroll
    for (int tm = 0; tm < 2; tm++)
        #pragma unroll
        for (int tn = 0; tn < 8; tn++)
            #pragma unroll
            for (int q = 0; q < 4; q++) acc[tm][tn][q] = 0.f;

    #define G1_LOAD(kb, buf) do {                                              \
        int k0 = (kb) * KB;                                                    \
        const __half* A = g_at + (size_t)(bi * 128) * MSA_S + k0;              \
        const __half* B = g_bt + (size_t)(bj * 128) * MSA_S + k0;              \
        uint32_t sA = sbase + (buf) * 2 * TB, sB = sA + TB;                    \
        _Pragma("unroll")                                                      \
        for (int it = 0; it < 2; it++) {                                       \
            int idx = tid + it * 256, r = idx >> 2, ch = idx & 3;              \
            cp16(sA + r * PITCH + ch * 16, A + (size_t)r * MSA_S + ch * 8);    \
            cp16(sB + r * PITCH + ch * 16, B + (size_t)r * MSA_S + ch * 8);    \
        }                                                                      \
        asm volatile("cp.async.commit_group;" ::: "memory");                   \
    } while (0)

    G1_LOAD(0, 0);
    for (int kb = 0; kb < 8; kb++) {
        int buf = kb & 1;
        if (kb + 1 < 8) {
            G1_LOAD(kb + 1, buf ^ 1);
            asm volatile("cp.async.wait_group 1;" ::: "memory");
        } else {
            asm volatile("cp.async.wait_group 0;" ::: "memory");
        }
        __syncthreads();
        uint32_t sA = sbase + buf * 2 * TB, sB = sA + TB;
        #pragma unroll
        for (int ks = 0; ks < 2; ks++) {
            uint32_t a[2][4];
            #pragma unroll
            for (int tm = 0; tm < 2; tm++)
                ldsm4(a[tm], sA + (wm * 32 + tm * 16 + (lane & 15)) * PITCH
                             + ks * 32 + (lane >> 4) * 16);
            uint32_t b[8][2];
            #pragma unroll
            for (int tq = 0; tq < 4; tq++) {
                uint32_t r[4];
                ldsm4(r, sB + (wn * 64 + tq * 16 + ((lane >> 4) << 3) + (lane & 7)) * PITCH
                         + ks * 32 + ((lane >> 3) & 1) * 16);
                b[2 * tq][0] = r[0]; b[2 * tq][1] = r[1];
                b[2 * tq + 1][0] = r[2]; b[2 * tq + 1][1] = r[3];
            }
            #pragma unroll
            for (int tm = 0; tm < 2; tm++)
                #pragma unroll
                for (int tn = 0; tn < 8; tn++)
                    mma16816(acc[tm][tn], a[tm], b[tn]);
        }
        __syncthreads();
    }

    // epilogue: scale, convert fp16, scatter to [pair][cd]
    const float invS = 1.0f / MSA_S;
    const int r0 = lane >> 2, cp2 = (lane & 3) * 2;
    #pragma unroll
    for (int tm = 0; tm < 2; tm++) {
        #pragma unroll
        for (int tn = 0; tn < 8; tn++) {
            int jd = bj * 128 + wn * 64 + tn * 8 + cp2;
            int pcol = jd >> 5, d = jd & 31;
            #pragma unroll
            for (int h = 0; h < 2; h++) {
                int ic = bi * 128 + wm * 32 + tm * 16 + r0 + h * 8;
                __half2 hv;
                hv.x = __float2half(acc[tm][tn][2 * h]     * invS);
                hv.y = __float2half(acc[tm][tn][2 * h + 1] * invS);
                size_t off = ((size_t)(ic >> 5) * NRES + pcol) * CD
                             + (ic & 31) * 32 + d;
                *(__half2*)(g_o + off) = hv;
            }
        }
    }
    #undef G1_LOAD
}

// -------------------------------------------------------------------------
// Kernel 5 (GEMM2, fp16 mma.sync): z[m,e] = O[m,:] @ W3t[e,:]^T + b3
// M = 147456, N = 128, K = 1024. CTA 128x128, warp tile 32x64.
// -------------------------------------------------------------------------
__global__ void __launch_bounds__(256, 2)
gemm2_mma(const float* __restrict__ b3, float* __restrict__ z) {
    __shared__ __align__(16) char smem[4 * TB];

    const int mb = blockIdx.x;
    const int tid = threadIdx.x, lane = tid & 31, wid = tid >> 5;
    const int wm = wid & 3, wn = wid >> 2;
    const uint32_t sbase = smem_u32(smem);

    float acc[2][8][4];
    #pragma unroll
    for (int tm = 0; tm < 2; tm++)
        #pragma unroll
        for (int tn = 0; tn < 8; tn++)
            #pragma unroll
            for (int q = 0; q < 4; q++) acc[tm][tn][q] = 0.f;

    #define G2_LOAD(kb, buf) do {                                              \
        int k0 = (kb) * KB;                                                    \
        const __half* A = g_o + (size_t)(mb * 128) * CD + k0;                  \
        const __half* B = g_w3t + k0;                                          \
        uint32_t sA = sbase + (buf) * 2 * TB, sB = sA + TB;                    \
        _Pragma("unroll")                                                      \
        for (int it = 0; it < 2; it++) {                                       \
            int idx = tid + it * 256, r = idx >> 2, ch = idx & 3;              \
            cp16(sA + r * PITCH + ch * 16, A + (size_t)r * CD + ch * 8);       \
            cp16(sB + r * PITCH + ch * 16, B + (size_t)r * CD + ch * 8);       \
        }                                                                      \
        asm volatile("cp.async.commit_group;" ::: "memory");                   \
    } while (0)

    G2_LOAD(0, 0);
    for (int kb = 0; kb < 32; kb++) {
        int buf = kb & 1;
        if (kb + 1 < 32) {
            G2_LOAD(kb + 1, buf ^ 1);
            asm volatile("cp.async.wait_group 1;" ::: "memory");
        } else {
            asm volatile("cp.async.wait_group 0;" ::: "memory");
        }
        __syncthreads();
        uint32_t sA = sbase + buf * 2 * TB, sB = sA + TB;
        #pragma unroll
        for (int ks = 0; ks < 2; ks++) {
            uint32_t a[2][4];
            #pragma unroll
            for (int tm = 0; tm < 2; tm++)
                ldsm4(a[tm], sA + (wm * 32 + tm * 16 + (lane & 15)) * PITCH
                             + ks * 32 + (lane >> 4) * 16);
            uint32_t b[8][2];
            #pragma unroll
            for (int tq = 0; tq < 4; tq++) {
                uint32_t r[4];
                ldsm4(r, sB + (wn * 64 + tq * 16 + ((lane >> 4) << 3) + (lane & 7)) * PITCH
                         + ks * 32 + ((lane >> 3) & 1) * 16);
                b[2 * tq][0] = r[0]; b[2 * tq][1] = r[1];
                b[2 * tq + 1][0] = r[2]; b[2 * tq + 1][1] = r[3];
            }
            #pragma unroll
            for (int tm = 0; tm < 2; tm++)
                #pragma unroll
                for (int tn = 0; tn < 8; tn++)
                    mma16816(acc[tm][tn], a[tm], b[tn]);
        }
        __syncthreads();
    }

    const int r0 = lane >> 2, cp2 = (lane & 3) * 2;
    #pragma unroll
    for (int tm = 0; tm < 2; tm++) {
        #pragma unroll
        for (int tn = 0; tn < 8; tn++) {
            int e = wn * 64 + tn * 8 + cp2;
            float be0 = __ldg(b3 + e), be1 = __ldg(b3 + e + 1);
            #pragma unroll
            for (int h = 0; h < 2; h++) {
                size_t mrow = (size_t)mb * 128 + wm * 32 + tm * 16 + r0 + h * 8;
                float2 v;
                v.x = acc[tm][tn][2 * h]     + be0;
                v.y = acc[tm][tn][2 * h + 1] + be1;
                *(float2*)(z + mrow * CZ + e) = v;
            }
        }
    }
    #undef G2_LOAD
}

// -------------------------------------------------------------------------
extern "C" void kernel_launch(void* const* d_in, const int* in_sizes, int n_in,
                              void* d_out, int out_size) {
    const float* m     = (const float*)d_in[0];
    const float* gamma = (const float*)d_in[1];
    const float* beta  = (const float*)d_in[2];
    const float* W1    = (const float*)d_in[3];
    const float* W2    = (const float*)d_in[4];
    const float* W3    = (const float*)d_in[5];
    const float* b3    = (const float*)d_in[6];
    float* z = (float*)d_out;
    (void)in_sizes; (void)n_in; (void)out_size;

    ln_proj_kernel<<<(MSA_S * NRES) / 8, dim3(32, 8)>>>(m, gamma, beta, W1, W2);
    transpose_half_ab<<<dim3(IC / 32, MSA_S / 32, 2), dim3(32, 8)>>>();
    transpose_half_w3<<<dim3(CD / 32, CZ / 32), dim3(32, 8)>>>(W3);
    gemm1_mma<<<dim3(IC / 128, IC / 128), 256>>>();
    gemm2_mma<<<NPAIR / 128, 256>>>(b3, z);
}

// round 6
// speedup vs baseline: 11.7493x; 1.0131x over previous
#include <cuda_runtime.h>
#include <cuda_fp16.h>
#include <cstdint>

#define MSA_S 256
#define NRES  384
#define C     32
#define CZ    128
#define IC    (NRES * C)          // 12288
#define NPAIR (NRES * NRES)       // 147456
#define CD    (C * C)             // 1024

// ------------------------------ scratch ----------------------------------
__device__ float g_a[MSA_S * IC];                  // LN(m)@W1  [s][ic]
__device__ float g_b[MSA_S * IC];                  // LN(m)@W2  [s][ic]
__device__ __half g_at[IC * MSA_S];                // [ic][s] fp16
__device__ __half g_bt[IC * MSA_S];
__device__ __half g_w3t[CZ * CD];                  // [e][cd] fp16
__device__ __half g_o[(size_t)NPAIR * CD];         // 302 MB fp16

// --------------------------- helpers -------------------------------------
__device__ __forceinline__ uint32_t smem_u32(const void* p) {
    uint32_t a;
    asm("{ .reg .u64 t; cvta.to.shared.u64 t, %1; cvt.u32.u64 %0, t; }"
        : "=r"(a) : "l"(p));
    return a;
}
__device__ __forceinline__ void cp16(uint32_t saddr, const void* g) {
    asm volatile("cp.async.cg.shared.global [%0], [%1], 16;"
                 :: "r"(saddr), "l"(g) : "memory");
}
__device__ __forceinline__ void ldsm4(uint32_t* r, uint32_t addr) {
    asm volatile("ldmatrix.sync.aligned.m8n8.x4.shared.b16 {%0,%1,%2,%3}, [%4];"
                 : "=r"(r[0]), "=r"(r[1]), "=r"(r[2]), "=r"(r[3]) : "r"(addr));
}
__device__ __forceinline__ void mma16816(float* d, const uint32_t* a,
                                         const uint32_t* b) {
    asm volatile(
        "mma.sync.aligned.m16n8k16.row.col.f32.f16.f16.f32 "
        "{%0,%1,%2,%3}, {%4,%5,%6,%7}, {%8,%9}, {%0,%1,%2,%3};"
        : "+f"(d[0]), "+f"(d[1]), "+f"(d[2]), "+f"(d[3])
        : "r"(a[0]), "r"(a[1]), "r"(a[2]), "r"(a[3]), "r"(b[0]), "r"(b[1]));
}

#define KB     32
#define PITCH  80                 // bytes per smem row (32 fp16 + 16B pad)
#define TB     (128 * PITCH)      // 10240 B per tile buffer

// -------------------------------------------------------------------------
// Kernel 1: fused LayerNorm + dual projection. One warp per (s,i) row.
// -------------------------------------------------------------------------
__global__ void ln_proj_kernel(const float* __restrict__ m,
                               const float* __restrict__ gamma,
                               const float* __restrict__ beta,
                               const float* __restrict__ W1,
                               const float* __restrict__ W2) {
    int row  = blockIdx.x * blockDim.y + threadIdx.y;
    int lane = threadIdx.x;

    float v = m[row * C + lane];
    float s = v;
    #pragma unroll
    for (int o = 16; o; o >>= 1) s += __shfl_xor_sync(0xffffffffu, s, o);
    float mu = s * (1.0f / C);
    float d  = v - mu;
    float q  = d * d;
    #pragma unroll
    for (int o = 16; o; o >>= 1) q += __shfl_xor_sync(0xffffffffu, q, o);
    float rstd = rsqrtf(q * (1.0f / C) + 1e-5f);
    float mn = d * rstd * gamma[lane] + beta[lane];

    float accA = 0.f, accB = 0.f;
    #pragma unroll
    for (int c = 0; c < C; c++) {
        float mv = __shfl_sync(0xffffffffu, mn, c);
        accA += mv * W1[c * C + lane];
        accB += mv * W2[c * C + lane];
    }
    g_a[row * C + lane] = accA;
    g_b[row * C + lane] = accB;
}

// -------------------------------------------------------------------------
// Kernel 2: transpose [s][ic] fp32 -> [ic][s] fp16 (a and b)
// -------------------------------------------------------------------------
__global__ void transpose_half_ab() {
    __shared__ float tile[32][33];
    const float* src = blockIdx.z ? g_b : g_a;
    __half* dst = blockIdx.z ? g_bt : g_at;
    int ic0 = blockIdx.x * 32, s0 = blockIdx.y * 32;
    int tx = threadIdx.x, ty = threadIdx.y;
    #pragma unroll
    for (int j = 0; j < 4; j++)
        tile[ty + j * 8][tx] = src[(size_t)(s0 + ty + j * 8) * IC + ic0 + tx];
    __syncthreads();
    #pragma unroll
    for (int j = 0; j < 4; j++) {
        size_t o = (size_t)(ic0 + ty + j * 8) * MSA_S + s0 + tx;
        dst[o] = __float2half(tile[tx][ty + j * 8]);
    }
}

// -------------------------------------------------------------------------
// Kernel 3: W3 [cd][e] -> W3t [e][cd] fp16
// -------------------------------------------------------------------------
__global__ void transpose_half_w3(const float* __restrict__ W3) {
    __shared__ float tile[32][33];
    int cd0 = blockIdx.x * 32, e0 = blockIdx.y * 32;
    int tx = threadIdx.x, ty = threadIdx.y;
    #pragma unroll
    for (int j = 0; j < 4; j++)
        tile[ty + j * 8][tx] = W3[(size_t)(cd0 + ty + j * 8) * CZ + e0 + tx];
    __syncthreads();
    #pragma unroll
    for (int j = 0; j < 4; j++) {
        size_t o = (size_t)(e0 + ty + j * 8) * CD + cd0 + tx;
        g_w3t[o] = __float2half(tile[tx][ty + j * 8]);
    }
}

// -------------------------------------------------------------------------
// Kernel 4 (GEMM1): O[ic, jd] = (1/S) sum_k at[ic,k] bt[jd,k]
// K = 256. CTA 128x128, 4 warps (2x2), warp tile 64x64.
// -------------------------------------------------------------------------
__global__ void __launch_bounds__(128, 2)
gemm1_mma() {
    __shared__ __align__(16) char smem[4 * TB];   // {A0,B0,A1,B1}

    const int bi = blockIdx.y, bj = blockIdx.x;
    const int tid = threadIdx.x, lane = tid & 31, wid = tid >> 5;
    const int wm = wid & 1, wn = wid >> 1;
    const uint32_t sbase = smem_u32(smem);

    float acc[4][8][4];
    #pragma unroll
    for (int tm = 0; tm < 4; tm++)
        #pragma unroll
        for (int tn = 0; tn < 8; tn++)
            #pragma unroll
            for (int q = 0; q < 4; q++) acc[tm][tn][q] = 0.f;

    #define G1_LOAD(kb, buf) do {                                              \
        int k0 = (kb) * KB;                                                    \
        const __half* A = g_at + (size_t)(bi * 128) * MSA_S + k0;              \
        const __half* B = g_bt + (size_t)(bj * 128) * MSA_S + k0;              \
        uint32_t sA = sbase + (buf) * 2 * TB, sB = sA + TB;                    \
        _Pragma("unroll")                                                      \
        for (int it = 0; it < 4; it++) {                                       \
            int idx = tid + it * 128, r = idx >> 2, ch = idx & 3;              \
            cp16(sA + r * PITCH + ch * 16, A + (size_t)r * MSA_S + ch * 8);    \
            cp16(sB + r * PITCH + ch * 16, B + (size_t)r * MSA_S + ch * 8);    \
        }                                                                      \
        asm volatile("cp.async.commit_group;" ::: "memory");                   \
    } while (0)

    G1_LOAD(0, 0);
    for (int kb = 0; kb < 8; kb++) {
        int buf = kb & 1;
        if (kb + 1 < 8) {
            G1_LOAD(kb + 1, buf ^ 1);
            asm volatile("cp.async.wait_group 1;" ::: "memory");
        } else {
            asm volatile("cp.async.wait_group 0;" ::: "memory");
        }
        __syncthreads();
        uint32_t sA = sbase + buf * 2 * TB, sB = sA + TB;
        #pragma unroll
        for (int ks = 0; ks < 2; ks++) {
            uint32_t a[4][4];
            #pragma unroll
            for (int tm = 0; tm < 4; tm++)
                ldsm4(a[tm], sA + (wm * 64 + tm * 16 + (lane & 15)) * PITCH
                             + ks * 32 + (lane >> 4) * 16);
            uint32_t b[8][2];
            #pragma unroll
            for (int tq = 0; tq < 4; tq++) {
                uint32_t r[4];
                ldsm4(r, sB + (wn * 64 + tq * 16 + ((lane >> 4) << 3) + (lane & 7)) * PITCH
                         + ks * 32 + ((lane >> 3) & 1) * 16);
                b[2 * tq][0] = r[0]; b[2 * tq][1] = r[1];
                b[2 * tq + 1][0] = r[2]; b[2 * tq + 1][1] = r[3];
            }
            #pragma unroll
            for (int tm = 0; tm < 4; tm++)
                #pragma unroll
                for (int tn = 0; tn < 8; tn++)
                    mma16816(acc[tm][tn], a[tm], b[tn]);
        }
        __syncthreads();
    }

    // epilogue: scale, convert fp16, scatter to [pair][cd]
    const float invS = 1.0f / MSA_S;
    const int r0 = lane >> 2, cp2 = (lane & 3) * 2;
    #pragma unroll
    for (int tm = 0; tm < 4; tm++) {
        #pragma unroll
        for (int tn = 0; tn < 8; tn++) {
            int jd = bj * 128 + wn * 64 + tn * 8 + cp2;
            int pcol = jd >> 5, d = jd & 31;
            #pragma unroll
            for (int h = 0; h < 2; h++) {
                int ic = bi * 128 + wm * 64 + tm * 16 + r0 + h * 8;
                __half2 hv;
                hv.x = __float2half(acc[tm][tn][2 * h]     * invS);
                hv.y = __float2half(acc[tm][tn][2 * h + 1] * invS);
                size_t off = ((size_t)(ic >> 5) * NRES + pcol) * CD
                             + (ic & 31) * 32 + d;
                *(__half2*)(g_o + off) = hv;
            }
        }
    }
    #undef G1_LOAD
}

// -------------------------------------------------------------------------
// Kernel 5 (GEMM2): z[m,e] = O[m,:] @ W3t[e,:]^T + b3
// M = 147456, N = 128, K = 1024. CTA 128x128, 4 warps, warp tile 64x64.
// -------------------------------------------------------------------------
__global__ void __launch_bounds__(128, 2)
gemm2_mma(const float* __restrict__ b3, float* __restrict__ z) {
    __shared__ __align__(16) char smem[4 * TB];

    const int mb = blockIdx.x;
    const int tid = threadIdx.x, lane = tid & 31, wid = tid >> 5;
    const int wm = wid & 1, wn = wid >> 1;
    const uint32_t sbase = smem_u32(smem);

    float acc[4][8][4];
    #pragma unroll
    for (int tm = 0; tm < 4; tm++)
        #pragma unroll
        for (int tn = 0; tn < 8; tn++)
            #pragma unroll
            for (int q = 0; q < 4; q++) acc[tm][tn][q] = 0.f;

    #define G2_LOAD(kb, buf) do {                                              \
        int k0 = (kb) * KB;                                                    \
        const __half* A = g_o + (size_t)(mb * 128) * CD + k0;                  \
        const __half* B = g_w3t + k0;                                          \
        uint32_t sA = sbase + (buf) * 2 * TB, sB = sA + TB;                    \
        _Pragma("unroll")                                                      \
        for (int it = 0; it < 4; it++) {                                       \
            int idx = tid + it * 128, r = idx >> 2, ch = idx & 3;              \
            cp16(sA + r * PITCH + ch * 16, A + (size_t)r * CD + ch * 8);       \
            cp16(sB + r * PITCH + ch * 16, B + (size_t)r * CD + ch * 8);       \
        }                                                                      \
        asm volatile("cp.async.commit_group;" ::: "memory");                   \
    } while (0)

    G2_LOAD(0, 0);
    for (int kb = 0; kb < 32; kb++) {
        int buf = kb & 1;
        if (kb + 1 < 32) {
            G2_LOAD(kb + 1, buf ^ 1);
            asm volatile("cp.async.wait_group 1;" ::: "memory");
        } else {
            asm volatile("cp.async.wait_group 0;" ::: "memory");
        }
        __syncthreads();
        uint32_t sA = sbase + buf * 2 * TB, sB = sA + TB;
        #pragma unroll
        for (int ks = 0; ks < 2; ks++) {
            uint32_t a[4][4];
            #pragma unroll
            for (int tm = 0; tm < 4; tm++)
                ldsm4(a[tm], sA + (wm * 64 + tm * 16 + (lane & 15)) * PITCH
                             + ks * 32 + (lane >> 4) * 16);
            uint32_t b[8][2];
            #pragma unroll
            for (int tq = 0; tq < 4; tq++) {
                uint32_t r[4];
                ldsm4(r, sB + (wn * 64 + tq * 16 + ((lane >> 4) << 3) + (lane & 7)) * PITCH
                         + ks * 32 + ((lane >> 3) & 1) * 16);
                b[2 * tq][0] = r[0]; b[2 * tq][1] = r[1];
                b[2 * tq + 1][0] = r[2]; b[2 * tq + 1][1] = r[3];
            }
            #pragma unroll
            for (int tm = 0; tm < 4; tm++)
                #pragma unroll
                for (int tn = 0; tn < 8; tn++)
                    mma16816(acc[tm][tn], a[tm], b[tn]);
        }
        __syncthreads();
    }

    const int r0 = lane >> 2, cp2 = (lane & 3) * 2;
    #pragma unroll
    for (int tm = 0; tm < 4; tm++) {
        #pragma unroll
        for (int tn = 0; tn < 8; tn++) {
            int e = wn * 64 + tn * 8 + cp2;
            float be0 = __ldg(b3 + e), be1 = __ldg(b3 + e + 1);
            #pragma unroll
            for (int h = 0; h < 2; h++) {
                size_t mrow = (size_t)mb * 128 + wm * 64 + tm * 16 + r0 + h * 8;
                float2 v;
                v.x = acc[tm][tn][2 * h]     + be0;
                v.y = acc[tm][tn][2 * h + 1] + be1;
                *(float2*)(z + mrow * CZ + e) = v;
            }
        }
    }
    #undef G2_LOAD
}

// -------------------------------------------------------------------------
extern "C" void kernel_launch(void* const* d_in, const int* in_sizes, int n_in,
                              void* d_out, int out_size) {
    const float* m     = (const float*)d_in[0];
    const float* gamma = (const float*)d_in[1];
    const float* beta  = (const float*)d_in[2];
    const float* W1    = (const float*)d_in[3];
    const float* W2    = (const float*)d_in[4];
    const float* W3    = (const float*)d_in[5];
    const float* b3    = (const float*)d_in[6];
    float* z = (float*)d_out;
    (void)in_sizes; (void)n_in; (void)out_size;

    ln_proj_kernel<<<(MSA_S * NRES) / 8, dim3(32, 8)>>>(m, gamma, beta, W1, W2);
    transpose_half_ab<<<dim3(IC / 32, MSA_S / 32, 2), dim3(32, 8)>>>();
    transpose_half_w3<<<dim3(CD / 32, CZ / 32), dim3(32, 8)>>>(W3);
    gemm1_mma<<<dim3(IC / 128, IC / 128), 128>>>();
    gemm2_mma<<<NPAIR / 128, 128>>>(b3, z);
}